// round 3
// baseline (speedup 1.0000x reference)
#include <cuda_runtime.h>

#define BATCH 4096
#define FEAT  512
#define NUMC  10000

#define BLOCK_THREADS 256
#define WARPS_PER_BLOCK (BLOCK_THREADS / 32)
#define GRID_BLOCKS (BATCH / WARPS_PER_BLOCK)   // 512

// Scratch (no cudaMalloc allowed)
__device__ float g_partials[BATCH];
__device__ int   g_count;   // zero-initialized; reset by last block each run

__global__ void __launch_bounds__(BLOCK_THREADS)
center_loss_kernel(const float* __restrict__ x,
                   const int*   __restrict__ labels32,
                   const float* __restrict__ centers,
                   float*       __restrict__ out) {
    const int lane = threadIdx.x & 31;
    const int warp = (blockIdx.x * BLOCK_THREADS + threadIdx.x) >> 5;  // row b

    // ---- issue ALL independent loads up front -------------------------------
    // dtype probe (odd words zero <=> labels are int64; P(false pos)=1e-128)
    int probe = __ldg(&labels32[2 * lane + 1]);
    int labA  = __ldg(&labels32[2 * warp]);   // candidate if int64
    int labB  = __ldg(&labels32[warp]);       // candidate if int32

    const float4* xr = reinterpret_cast<const float4*>(x + (size_t)warp * FEAT);
    float4 xv[4];
#pragma unroll
    for (int i = 0; i < 4; i++) xv[i] = __ldg(&xr[lane + 32 * i]);

    bool is64 = (__ballot_sync(0xffffffffu, probe != 0) == 0u);
    int  lab  = is64 ? labA : labB;

    const float4* cr = reinterpret_cast<const float4*>(centers + (size_t)lab * FEAT);
    float4 cv[4];
#pragma unroll
    for (int i = 0; i < 4; i++) cv[i] = __ldg(&cr[lane + 32 * i]);

    // ---- 4 independent accumulators (no serial FMA chain) -------------------
    float a0 = 0.f, a1 = 0.f, a2 = 0.f, a3 = 0.f;
#pragma unroll
    for (int i = 0; i < 4; i++) {
        float d0 = xv[i].x - cv[i].x;
        float d1 = xv[i].y - cv[i].y;
        float d2 = xv[i].z - cv[i].z;
        float d3 = xv[i].w - cv[i].w;
        a0 = fmaf(d0, d0, a0);
        a1 = fmaf(d1, d1, a1);
        a2 = fmaf(d2, d2, a2);
        a3 = fmaf(d3, d3, a3);
    }
    float acc = (a0 + a1) + (a2 + a3);
#pragma unroll
    for (int o = 16; o > 0; o >>= 1)
        acc += __shfl_xor_sync(0xffffffffu, acc, o);

    if (lane == 0) {
        g_partials[warp] = fminf(fmaxf(acc, 1e-12f), 1e12f);  // clip on diagonal
        __threadfence();
    }

    // ---- last-block-done deterministic reduction ----------------------------
    __shared__ bool is_last;
    __syncthreads();
    if (threadIdx.x == 0) {
        int c = atomicAdd(&g_count, 1);
        is_last = (c == GRID_BLOCKS - 1);
    }
    __syncthreads();

    if (is_last) {
        __shared__ float sh[WARPS_PER_BLOCK];
        float s = 0.0f;
#pragma unroll
        for (int i = 0; i < BATCH / BLOCK_THREADS; i++)
            s += g_partials[threadIdx.x + i * BLOCK_THREADS];
#pragma unroll
        for (int o = 16; o > 0; o >>= 1)
            s += __shfl_xor_sync(0xffffffffu, s, o);
        if (lane == 0) sh[threadIdx.x >> 5] = s;
        __syncthreads();
        if (threadIdx.x == 0) {
            float tot = 0.0f;
#pragma unroll
            for (int w = 0; w < WARPS_PER_BLOCK; w++) tot += sh[w];
            float base = (float)((double)(NUMC - 1) * 1e-12); // clipped masked zeros
            out[0] = tot / (float)BATCH + base;
            g_count = 0;  // replay-safe reset
        }
    }
}

extern "C" void kernel_launch(void* const* d_in, const int* in_sizes, int n_in,
                              void* d_out, int out_size) {
    const float* x       = (const float*)d_in[0];
    const int*   labels  = (const int*)  d_in[1];
    const float* centers = (const float*)d_in[2];
    float*       out     = (float*)d_out;

    center_loss_kernel<<<GRID_BLOCKS, BLOCK_THREADS>>>(x, labels, centers, out);
}